// round 3
// baseline (speedup 1.0000x reference)
#include <cuda_runtime.h>
#include <math.h>

#define BATCH 64
#define NS 4096
#define NBLK 16

// scratch (device globals; no allocations allowed)
__device__ float g_h [BATCH * NS];
__device__ float g_da[BATCH * NS];
__device__ float g_db[BATCH * NS];
__device__ float g_part[BATCH][NBLK][22];
__device__ float g_c01[BATCH * 2];

__device__ __forceinline__ void gelu3f(float x, float& v, float& d1, float& d2) {
    // exact-erf GELU: v = x*Phi(x), d1 = Phi + x*phi, d2 = (2 - x^2)*phi
    float Phi = normcdff(x);
    float ph  = 0.3989422804014326779f * __expf(-0.5f * x * x);
    v  = x * Phi;
    d1 = fmaf(x, ph, Phi);
    d2 = (2.0f - x * x) * ph;
}

#define WRED(a) { a += __shfl_xor_sync(0xffffffffu,a,16); a += __shfl_xor_sync(0xffffffffu,a,8); \
                  a += __shfl_xor_sync(0xffffffffu,a,4);  a += __shfl_xor_sync(0xffffffffu,a,2); \
                  a += __shfl_xor_sync(0xffffffffu,a,1); }

// ---------------------------------------------------------------------------
// Pass A: per-site forward + 4 tangent matvecs through W2.
// grid (NBLK, BATCH), block 256 (8 warps), warp-per-site, 32 sites per warp.
// ---------------------------------------------------------------------------
__global__ void __launch_bounds__(256, 1)
passA_kernel(const float* __restrict__ x, const int* __restrict__ signs,
             const float* __restrict__ W1, const float* __restrict__ b1,
             const float* __restrict__ W2, const float* __restrict__ b2,
             const float* __restrict__ W3, const float* __restrict__ b3)
{
    extern __shared__ char sm[];
    float*  W2s  = (float*) sm;                 // 65536 B : W2 row-major [j*128+k]
    float4* sv4  = (float4*)(sm + 65536);       // 16384 B : 8 warps x 128 float4 (a1,va,vb,u1)
    float*  su2  = (float*) (sm + 81920);       //  4096 B : 8 warps x 128 (u2)
    float*  was  = (float*) (sm + 86016);       //   512 B
    float*  wbs  = (float*) (sm + 86528);
    float*  b1s  = (float*) (sm + 87040);
    float*  b2s  = (float*) (sm + 87552);
    float*  w3s  = (float*) (sm + 88064);
    float*  wpart= (float*) (sm + 88576);       //   704 B : 8 warps x 22

    const int tid  = threadIdx.x;
    const int warp = tid >> 5;
    const int lane = tid & 31;
    const int b    = blockIdx.y;

    for (int idx = tid; idx < 128 * 128; idx += 256) W2s[idx] = W2[idx];
    if (tid < 128) {
        was[tid] = W1[tid] + W1[256 + tid] + W1[384 + tid];
        wbs[tid] = W1[128 + tid];
        b1s[tid] = b1[tid];
        b2s[tid] = b2[tid];
        w3s[tid] = W3[tid];
    }
    __syncthreads();

    const float  b3v = b3[0];
    const float* xb  = x + b * NS;
    const int*   sgb = signs + b * NS;   // color c at +c*BATCH*NS

    // deterministic per-warp partials (22)
    float aSh = 0.0f, aSh2 = 0.0f;
    float aHd[4]  = {0,0,0,0}, aH2[4]  = {0,0,0,0}, aHd2[4] = {0,0,0,0};
    float aHHd[4] = {0,0,0,0}, aHH2[4] = {0,0,0,0};

    float4* mv4 = sv4 + warp * 128;
    float*  mu2 = su2 + warp * 128;

    for (int it = 0; it < 32; ++it) {
        const int s  = blockIdx.x * 256 + it * 8 + warp;
        const int i  = s >> 6, j = s & 63;
        const int iM = (i + 63) & 63, iP = (i + 1) & 63;
        const int jM = (j + 63) & 63, jP = (j + 1) & 63;

        const float xc  = xb[s];
        const float lap = xb[(iM << 6) | j] + xb[(iP << 6) | j]
                        + xb[(i << 6) | jM] + xb[(i << 6) | jP] - 4.0f * xc;

        const int d = ((i & 1) << 1) | (j & 1);
        const float alpha = (float)(2 * sgb[d * (BATCH * NS) + s] - 1);
        const float bet1  = (float)(2 * sgb[(d ^ 1) * (BATCH * NS) + ((i << 6) | jM)]
                                  + 2 * sgb[(d ^ 1) * (BATCH * NS) + ((i << 6) | jP)] - 2);
        const float bet2  = (float)(2 * sgb[(d ^ 2) * (BATCH * NS) + ((iM << 6) | j)]
                                  + 2 * sgb[(d ^ 2) * (BATCH * NS) + ((iP << 6) | j)] - 2);

        // layer 1: each lane computes 4 hidden units; build the 5 matvec inputs
        #pragma unroll
        for (int c = 0; c < 4; ++c) {
            const int jh = lane * 4 + c;
            const float waj = was[jh], wbj = wbs[jh];
            const float p1  = fmaf(xc, waj, fmaf(lap, wbj, b1s[jh]));
            float a1, gp, gpp;
            gelu3f(p1, a1, gp, gpp);
            const float wd = waj - 4.0f * wbj;
            mv4[jh] = make_float4(a1, gp * wd, gp * wbj, gpp * wd * wd);
            mu2[jh] = gpp * wbj * wbj;
        }
        __syncwarp();

        // fused 5-way matvec: out_k = sum_j vec_j * W2[j,k], lane owns k = lane*4..+3
        float accA[4] = {0,0,0,0}, accP[4] = {0,0,0,0}, accQ[4] = {0,0,0,0};
        float accR[4] = {0,0,0,0}, accS[4] = {0,0,0,0};
        #pragma unroll 8
        for (int jj = 0; jj < 128; ++jj) {
            const float4 v  = mv4[jj];
            const float  u2 = mu2[jj];
            const float4 w  = *reinterpret_cast<const float4*>(W2s + jj * 128 + lane * 4);
            accA[0] = fmaf(v.x, w.x, accA[0]); accA[1] = fmaf(v.x, w.y, accA[1]);
            accA[2] = fmaf(v.x, w.z, accA[2]); accA[3] = fmaf(v.x, w.w, accA[3]);
            accP[0] = fmaf(v.y, w.x, accP[0]); accP[1] = fmaf(v.y, w.y, accP[1]);
            accP[2] = fmaf(v.y, w.z, accP[2]); accP[3] = fmaf(v.y, w.w, accP[3]);
            accQ[0] = fmaf(v.z, w.x, accQ[0]); accQ[1] = fmaf(v.z, w.y, accQ[1]);
            accQ[2] = fmaf(v.z, w.z, accQ[2]); accQ[3] = fmaf(v.z, w.w, accQ[3]);
            accR[0] = fmaf(v.w, w.x, accR[0]); accR[1] = fmaf(v.w, w.y, accR[1]);
            accR[2] = fmaf(v.w, w.z, accR[2]); accR[3] = fmaf(v.w, w.w, accR[3]);
            accS[0] = fmaf(u2,  w.x, accS[0]); accS[1] = fmaf(u2,  w.y, accS[1]);
            accS[2] = fmaf(u2,  w.z, accS[2]); accS[3] = fmaf(u2,  w.w, accS[3]);
        }
        __syncwarp();   // protect mv4/mu2 before next iteration rewrites them

        // layer 2 + W3 dot products
        float hl = 0, Pd = 0, Qd = 0, PP = 0, QQ = 0, RR = 0, SS = 0;
        #pragma unroll
        for (int c = 0; c < 4; ++c) {
            const int k = lane * 4 + c;
            const float p2 = accA[c] + b2s[k];
            float a2, gp2, gpp2;
            gelu3f(p2, a2, gp2, gpp2);
            const float w3 = w3s[k];
            const float gw = gp2 * w3, gg = gpp2 * w3;
            hl = fmaf(a2, w3, hl);
            Pd = fmaf(accP[c], gw, Pd);
            Qd = fmaf(accQ[c], gw, Qd);
            RR = fmaf(accR[c], gw, RR);
            SS = fmaf(accS[c], gw, SS);
            PP = fmaf(accP[c] * accP[c], gg, PP);
            QQ = fmaf(accQ[c] * accQ[c], gg, QQ);
        }
        WRED(hl); WRED(Pd); WRED(Qd); WRED(PP); WRED(QQ); WRED(RR); WRED(SS);

        if (lane == 0) {
            const float h = hl + b3v;
            g_h [b * NS + s] = h;
            g_da[b * NS + s] = Pd + 4.0f * Qd;   // dF(site)/dx_s direction coeff
            g_db[b * NS + s] = Qd;               // dF(site)/dlap_s direction coeff
            aSh  += h;
            aSh2 += h * h;
            #pragma unroll
            for (int c = 0; c < 4; ++c) {
                float hd, h2;
                if      (c == d)        { hd = alpha * Pd; h2 = PP + RR; }
                else if (c == (d ^ 1))  { hd = bet1  * Qd; h2 = bet1 * bet1 * (QQ + SS); }
                else if (c == (d ^ 2))  { hd = bet2  * Qd; h2 = bet2 * bet2 * (QQ + SS); }
                else                    { hd = 0.0f;       h2 = 0.0f; }
                aHd [c] += hd;
                aH2 [c] += h2;
                aHd2[c] += hd * hd;
                aHHd[c] += h * hd;
                aHH2[c] += h * h2;
            }
        }
    }

    if (lane == 0) {
        float* wp = wpart + warp * 22;
        wp[0] = aSh; wp[1] = aSh2;
        #pragma unroll
        for (int c = 0; c < 4; ++c) {
            wp[2 + c]  = aHd [c];
            wp[6 + c]  = aH2 [c];
            wp[10 + c] = aHd2[c];
            wp[14 + c] = aHHd[c];
            wp[18 + c] = aHH2[c];
        }
    }
    __syncthreads();
    if (tid < 22) {
        float sum = 0.0f;
        #pragma unroll
        for (int w = 0; w < 8; ++w) sum += wpart[w * 22 + tid];
        g_part[b][blockIdx.x][tid] = sum;
    }
}

// ---------------------------------------------------------------------------
// Pass B: per-batch stats + agg MLP (backward scalars c0,c1 and second-order
// forward for the Laplacian estimate). grid BATCH, block 64. Double precision.
// ---------------------------------------------------------------------------
__global__ void passB_kernel(const float* __restrict__ aW1, const float* __restrict__ ab1,
                             const float* __restrict__ aW2, float* __restrict__ out)
{
    __shared__ double S[22];
    __shared__ double red0[64], red1[64], red2[64];

    const int b = blockIdx.x, t = threadIdx.x;
    if (t < 22) {
        double s = 0.0;
        for (int k = 0; k < NBLK; ++k) s += (double)g_part[b][k][t];
        S[t] = s;
    }
    __syncthreads();

    const double N = 4096.0, N1 = 4095.0;
    const double m = S[0] / N;
    const double q = S[1] / N;
    const double v = (S[1] - N * m * m) / N1;

    const double a0 = (double)aW1[t], a1 = (double)aW1[64 + t], a2 = (double)aW1[128 + t];
    const double u  = m * a0 + v * a1 + q * a2 + (double)ab1[t];
    const double Phi = normcdf(u);
    const double ph  = 0.39894228040143267794 * exp(-0.5 * u * u);
    const double gp  = Phi + u * ph;
    const double gpp = (2.0 - u * u) * ph;
    const double w2  = (double)aW2[t];

    red0[t] = a0 * gp * w2;
    red1[t] = a1 * gp * w2;
    red2[t] = a2 * gp * w2;
    __syncthreads();
    if (t == 0) {
        double dm = 0, dv = 0, dq = 0;
        for (int i = 0; i < 64; ++i) { dm += red0[i]; dv += red1[i]; dq += red2[i]; }
        const double c0 = dm / N - 2.0 * dv * m / N1;
        const double c1 = 2.0 * dv / N1 + 2.0 * dq / N;
        g_c01[2 * b]     = (float)c0;
        g_c01[2 * b + 1] = (float)c1;
    }
    __syncthreads();   // red0 free again

    // second-order forward for each color, accumulated per thread then reduced once
    double fac = 0.0;
    #pragma unroll
    for (int c = 0; c < 4; ++c) {
        const double md  = S[2 + c]  / N;
        const double mdd = S[6 + c]  / N;
        const double qd  = 2.0 *  S[14 + c] / N;
        const double qdd = 2.0 * (S[10 + c] + S[18 + c]) / N;
        const double vd  = 2.0 * (S[14 + c] - N * m * md) / N1;
        const double vdd = 2.0 * ((S[10 + c] - N * md * md) + (S[18 + c] - N * m * mdd)) / N1;
        const double ud  = md  * a0 + vd  * a1 + qd  * a2;
        const double udd = mdd * a0 + vdd * a1 + qdd * a2;
        fac += w2 * (gpp * ud * ud + gp * udd);
    }
    red0[t] = fac;
    __syncthreads();
    if (t == 0) {
        double L = 0.0;
        for (int i = 0; i < 64; ++i) L += red0[i];
        out[b * 4097 + 4096] = (float)L;
    }
}

// ---------------------------------------------------------------------------
// Pass C: grad = g*da + Stencil(g*db), g = c0 + c1*h. grid (16, BATCH), 256 thr.
// ---------------------------------------------------------------------------
__global__ void passC_kernel(float* __restrict__ out)
{
    const int b = blockIdx.y;
    const int s = blockIdx.x * 256 + threadIdx.x;
    const int i = s >> 6, j = s & 63;
    const int iM = (i + 63) & 63, iP = (i + 1) & 63;
    const int jM = (j + 63) & 63, jP = (j + 1) & 63;

    const float c0 = g_c01[2 * b], c1 = g_c01[2 * b + 1];
    const float* h  = g_h  + b * NS;
    const float* db = g_db + b * NS;

    const int nU = (iM << 6) | j, nD = (iP << 6) | j;
    const int nL = (i << 6) | jM, nR = (i << 6) | jP;

    const float gs = fmaf(c1, h[s], c0);
    const float st = fmaf(c1, h[nU], c0) * db[nU]
                   + fmaf(c1, h[nD], c0) * db[nD]
                   + fmaf(c1, h[nL], c0) * db[nL]
                   + fmaf(c1, h[nR], c0) * db[nR]
                   - 4.0f * gs * db[s];
    out[b * 4097 + s] = fmaf(gs, g_da[b * NS + s], st);
}

// ---------------------------------------------------------------------------
extern "C" void kernel_launch(void* const* d_in, const int* in_sizes, int n_in,
                              void* d_out, int out_size)
{
    (void)in_sizes; (void)n_in; (void)out_size;
    const float* x     = (const float*)d_in[0];
    const int*   signs = (const int*)  d_in[1];
    const float* W1    = (const float*)d_in[2];
    const float* b1    = (const float*)d_in[3];
    const float* W2    = (const float*)d_in[4];
    const float* b2    = (const float*)d_in[5];
    const float* W3    = (const float*)d_in[6];
    const float* b3    = (const float*)d_in[7];
    const float* aW1   = (const float*)d_in[8];
    const float* ab1   = (const float*)d_in[9];
    const float* aW2   = (const float*)d_in[10];
    float* out = (float*)d_out;

    cudaFuncSetAttribute(passA_kernel, cudaFuncAttributeMaxDynamicSharedMemorySize, 89280);

    passA_kernel<<<dim3(NBLK, BATCH), 256, 89280>>>(x, signs, W1, b1, W2, b2, W3, b3);
    passB_kernel<<<BATCH, 64>>>(aW1, ab1, aW2, out);
    passC_kernel<<<dim3(16, BATCH), 256>>>(out);
}

// round 5
// speedup vs baseline: 1.3291x; 1.3291x over previous
#include <cuda_runtime.h>
#include <math.h>

#define BATCH 64
#define NS 4096
#define NBLK 16
#define NPART 13

// scratch (device globals; no allocations allowed)
__device__ float g_h [BATCH * NS];
__device__ float g_da[BATCH * NS];
__device__ float g_db[BATCH * NS];
__device__ float g_part[BATCH][NBLK][NPART];
__device__ float g_c01[BATCH * 2];

__device__ __forceinline__ void gelu3f(float x, float& v, float& d1, float& d2) {
    // exact-erf GELU: v = x*Phi(x), d1 = Phi + x*phi, d2 = (2 - x^2)*phi
    float Phi = normcdff(x);
    float ph  = 0.3989422804014326779f * __expf(-0.5f * x * x);
    v  = x * Phi;
    d1 = fmaf(x, ph, Phi);
    d2 = (2.0f - x * x) * ph;
}

// packed f32x2 helpers (sm_100+/PTX ISA 8.6)
__device__ __forceinline__ unsigned long long dup2(float v) {
    unsigned long long r;
    asm("mov.b64 %0, {%1, %1};" : "=l"(r) : "f"(v));
    return r;
}
__device__ __forceinline__ void fma2(unsigned long long& d,
                                     unsigned long long a, unsigned long long b) {
    asm("fma.rn.f32x2 %0, %1, %2, %0;" : "+l"(d) : "l"(a), "l"(b));
}
__device__ __forceinline__ float2 unp2(unsigned long long a) {
    float2 f;
    asm("mov.b64 {%0, %1}, %2;" : "=f"(f.x), "=f"(f.y) : "l"(a));
    return f;
}

#define WRED(a) { a += __shfl_xor_sync(0xffffffffu,a,16); a += __shfl_xor_sync(0xffffffffu,a,8); \
                  a += __shfl_xor_sync(0xffffffffu,a,4);  a += __shfl_xor_sync(0xffffffffu,a,2); \
                  a += __shfl_xor_sync(0xffffffffu,a,1); }

// smem layout offsets (bytes)
#define OFF_W2S   0
#define OFF_SV4   65536
#define OFF_WAS   98304
#define OFF_WBS   98816
#define OFF_B1S   99328
#define OFF_B2S   99840
#define OFF_W3S   100352
#define OFF_WPART 100864
#define SMEMSZ    101280

// ---------------------------------------------------------------------------
// Pass A: per-site forward + 3 tangent matvecs (packed f32x2, 2 sites/warp).
// grid (NBLK, BATCH), block 256 (8 warps), 2 sites per warp per iter, 16 iters.
// ---------------------------------------------------------------------------
__global__ void __launch_bounds__(256, 1)
passA_kernel(const float* __restrict__ x, const int* __restrict__ signs,
             const float* __restrict__ W1, const float* __restrict__ b1,
             const float* __restrict__ W2, const float* __restrict__ b2,
             const float* __restrict__ W3, const float* __restrict__ b3)
{
    extern __shared__ char sm[];
    float*  W2s  = (float*) (sm + OFF_W2S);    // W2 row-major [j*128+k]
    float4* sv4  = (float4*)(sm + OFF_SV4);    // 8 warps x 2 sites x 128 float4
    float*  was  = (float*) (sm + OFF_WAS);
    float*  wbs  = (float*) (sm + OFF_WBS);
    float*  b1s  = (float*) (sm + OFF_B1S);
    float*  b2s  = (float*) (sm + OFF_B2S);
    float*  w3s  = (float*) (sm + OFF_W3S);
    float*  wpart= (float*) (sm + OFF_WPART);  // 8 warps x 13

    const int tid  = threadIdx.x;
    const int warp = tid >> 5;
    const int lane = tid & 31;
    const int b    = blockIdx.y;

    for (int idx = tid; idx < 128 * 128; idx += 256) W2s[idx] = W2[idx];
    if (tid < 128) {
        was[tid] = W1[tid] + W1[256 + tid] + W1[384 + tid];
        wbs[tid] = W1[128 + tid];
        b1s[tid] = b1[tid];
        b2s[tid] = b2[tid];
        w3s[tid] = W3[tid];
    }
    __syncthreads();

    const float  b3v = b3[0];
    const float* xb  = x + b * NS;
    const int*   sgb = signs + b * NS;   // color c at +c*BATCH*NS

    // deterministic per-warp partials (13)
    float aSh = 0.0f, aSh2 = 0.0f;
    float aHd[4]  = {0,0,0,0}, aHHd[4] = {0,0,0,0};
    float aH2s = 0.0f, aHd2s = 0.0f, aHH2s = 0.0f;

    float4* mv0 = sv4 + warp * 256;
    float4* mv1 = mv0 + 128;

    for (int it = 0; it < 16; ++it) {
        const int s0 = blockIdx.x * 256 + it * 16 + warp * 2;

        float alpha[2], bet1[2], bet2[2], s12[2];
        int   dcol[2];

        // ---- layer 1 for both sites: build packed (a1, gp*wd, gp*wb, u) ----
        #pragma unroll
        for (int sI = 0; sI < 2; ++sI) {
            const int s  = s0 + sI;
            const int i  = s >> 6, j = s & 63;
            const int iM = (i + 63) & 63, iP = (i + 1) & 63;
            const int jM = (j + 63) & 63, jP = (j + 1) & 63;

            const float xc  = xb[s];
            const float lap = xb[(iM << 6) | j] + xb[(iP << 6) | j]
                            + xb[(i << 6) | jM] + xb[(i << 6) | jP] - 4.0f * xc;

            const int d = ((i & 1) << 1) | (j & 1);
            dcol[sI]  = d;
            alpha[sI] = (float)(2 * sgb[d * (BATCH * NS) + s] - 1);
            bet1[sI]  = (float)(2 * sgb[(d ^ 1) * (BATCH * NS) + ((i << 6) | jM)]
                              + 2 * sgb[(d ^ 1) * (BATCH * NS) + ((i << 6) | jP)] - 2);
            bet2[sI]  = (float)(2 * sgb[(d ^ 2) * (BATCH * NS) + ((iM << 6) | j)]
                              + 2 * sgb[(d ^ 2) * (BATCH * NS) + ((iP << 6) | j)] - 2);
            const float sc = bet1[sI] * bet1[sI] + bet2[sI] * bet2[sI];
            s12[sI] = sc;

            float4* mv = sI ? mv1 : mv0;
            #pragma unroll
            for (int c = 0; c < 4; ++c) {
                const int jh = lane * 4 + c;
                const float waj = was[jh], wbj = wbs[jh];
                const float p1  = fmaf(xc, waj, fmaf(lap, wbj, b1s[jh]));
                float a1, gp, gpp;
                gelu3f(p1, a1, gp, gpp);
                const float wd = waj - 4.0f * wbj;
                const float u  = gpp * fmaf(sc, wbj * wbj, wd * wd);
                mv[jh] = make_float4(a1, gp * wd, gp * wbj, u);
            }
        }
        __syncwarp();

        // ---- fused 4-way matvec, 2 sites, packed f32x2 over k-pairs ----
        // acc[site][type][kpair]; lane owns k = lane*4 .. +3
        unsigned long long acc[2][4][2];
        #pragma unroll
        for (int sI = 0; sI < 2; ++sI)
            #pragma unroll
            for (int t = 0; t < 4; ++t) { acc[sI][t][0] = 0ull; acc[sI][t][1] = 0ull; }

        #pragma unroll 4
        for (int jj = 0; jj < 128; ++jj) {
            const ulonglong2 w = *reinterpret_cast<const ulonglong2*>(
                                     W2s + jj * 128 + lane * 4);
            const float4 v0 = mv0[jj];
            const float4 v1 = mv1[jj];
            unsigned long long dA, dP, dQ, dU;

            dA = dup2(v0.x); dP = dup2(v0.y); dQ = dup2(v0.z); dU = dup2(v0.w);
            fma2(acc[0][0][0], dA, w.x); fma2(acc[0][0][1], dA, w.y);
            fma2(acc[0][1][0], dP, w.x); fma2(acc[0][1][1], dP, w.y);
            fma2(acc[0][2][0], dQ, w.x); fma2(acc[0][2][1], dQ, w.y);
            fma2(acc[0][3][0], dU, w.x); fma2(acc[0][3][1], dU, w.y);

            dA = dup2(v1.x); dP = dup2(v1.y); dQ = dup2(v1.z); dU = dup2(v1.w);
            fma2(acc[1][0][0], dA, w.x); fma2(acc[1][0][1], dA, w.y);
            fma2(acc[1][1][0], dP, w.x); fma2(acc[1][1][1], dP, w.y);
            fma2(acc[1][2][0], dQ, w.x); fma2(acc[1][2][1], dQ, w.y);
            fma2(acc[1][3][0], dU, w.x); fma2(acc[1][3][1], dU, w.y);
        }
        __syncwarp();   // protect mv0/mv1 before next iteration rewrites them

        // ---- layer 2 + dot products, per site ----
        #pragma unroll
        for (int sI = 0; sI < 2; ++sI) {
            const int s = s0 + sI;
            float accA[4], accP[4], accQ[4], accU[4];
            {
                float2 t;
                t = unp2(acc[sI][0][0]); accA[0]=t.x; accA[1]=t.y;
                t = unp2(acc[sI][0][1]); accA[2]=t.x; accA[3]=t.y;
                t = unp2(acc[sI][1][0]); accP[0]=t.x; accP[1]=t.y;
                t = unp2(acc[sI][1][1]); accP[2]=t.x; accP[3]=t.y;
                t = unp2(acc[sI][2][0]); accQ[0]=t.x; accQ[1]=t.y;
                t = unp2(acc[sI][2][1]); accQ[2]=t.x; accQ[3]=t.y;
                t = unp2(acc[sI][3][0]); accU[0]=t.x; accU[1]=t.y;
                t = unp2(acc[sI][3][1]); accU[2]=t.x; accU[3]=t.y;
            }

            float hl = 0, Pd = 0, Qd = 0, PP = 0, QQ = 0, UU = 0;
            #pragma unroll
            for (int c = 0; c < 4; ++c) {
                const int k = lane * 4 + c;
                const float p2 = accA[c] + b2s[k];
                float a2, gp2, gpp2;
                gelu3f(p2, a2, gp2, gpp2);
                const float w3 = w3s[k];
                const float gw = gp2 * w3, gg = gpp2 * w3;
                hl = fmaf(a2, w3, hl);
                Pd = fmaf(accP[c], gw, Pd);
                Qd = fmaf(accQ[c], gw, Qd);
                UU = fmaf(accU[c], gw, UU);
                PP = fmaf(accP[c] * accP[c], gg, PP);
                QQ = fmaf(accQ[c] * accQ[c], gg, QQ);
            }
            WRED(hl); WRED(Pd); WRED(Qd); WRED(PP); WRED(QQ); WRED(UU);

            if (lane == 0) {
                const float h = hl + b3v;
                g_h [b * NS + s] = h;
                g_da[b * NS + s] = Pd + 4.0f * Qd;
                g_db[b * NS + s] = Qd;
                aSh  += h;
                aSh2 += h * h;

                const int   d  = dcol[sI];
                const float al = alpha[sI], bb1 = bet1[sI], bb2 = bet2[sI];
                #pragma unroll
                for (int c = 0; c < 4; ++c) {
                    float hd;
                    if      (c == d)       hd = al  * Pd;
                    else if (c == (d ^ 1)) hd = bb1 * Qd;
                    else if (c == (d ^ 2)) hd = bb2 * Qd;
                    else                   hd = 0.0f;
                    aHd [c] += hd;
                    aHHd[c] += h * hd;
                }
                const float sc  = s12[sI];
                const float h2t = PP + sc * QQ + UU;   // Σ_c h2_c (pre-weighted)
                aH2s  += h2t;
                aHd2s += fmaf(sc, Qd * Qd, Pd * Pd);   // Σ_c hd_c^2
                aHH2s += h * h2t;
            }
        }
    }

    if (lane == 0) {
        float* wp = wpart + warp * NPART;
        wp[0] = aSh; wp[1] = aSh2;
        #pragma unroll
        for (int c = 0; c < 4; ++c) {
            wp[2 + c] = aHd [c];
            wp[6 + c] = aHHd[c];
        }
        wp[10] = aH2s; wp[11] = aHd2s; wp[12] = aHH2s;
    }
    __syncthreads();
    if (tid < NPART) {
        float sum = 0.0f;
        #pragma unroll
        for (int w = 0; w < 8; ++w) sum += wpart[w * NPART + tid];
        g_part[b][blockIdx.x][tid] = sum;
    }
}

// ---------------------------------------------------------------------------
// Pass B: per-batch stats + agg MLP backward (c0,c1) + second-order forward
// for the Laplacian. grid BATCH, block 64. Double precision.
// ---------------------------------------------------------------------------
__global__ void passB_kernel(const float* __restrict__ aW1, const float* __restrict__ ab1,
                             const float* __restrict__ aW2, float* __restrict__ out)
{
    __shared__ double S[NPART];
    __shared__ double red0[64], red1[64], red2[64];

    const int b = blockIdx.x, t = threadIdx.x;
    if (t < NPART) {
        double s = 0.0;
        for (int k = 0; k < NBLK; ++k) s += (double)g_part[b][k][t];
        S[t] = s;
    }
    __syncthreads();

    const double N = 4096.0, N1 = 4095.0;
    const double m = S[0] / N;
    const double q = S[1] / N;
    const double v = (S[1] - N * m * m) / N1;

    const double a0 = (double)aW1[t], a1 = (double)aW1[64 + t], a2 = (double)aW1[128 + t];
    const double u  = m * a0 + v * a1 + q * a2 + (double)ab1[t];
    const double Phi = normcdf(u);
    const double ph  = 0.39894228040143267794 * exp(-0.5 * u * u);
    const double gp  = Phi + u * ph;
    const double gpp = (2.0 - u * u) * ph;
    const double w2  = (double)aW2[t];

    red0[t] = a0 * gp * w2;
    red1[t] = a1 * gp * w2;
    red2[t] = a2 * gp * w2;
    __syncthreads();
    if (t == 0) {
        double dm = 0, dv = 0, dq = 0;
        for (int i = 0; i < 64; ++i) { dm += red0[i]; dv += red1[i]; dq += red2[i]; }
        const double c0 = dm / N - 2.0 * dv * m / N1;
        const double c1 = 2.0 * dv / N1 + 2.0 * dq / N;
        g_c01[2 * b]     = (float)c0;
        g_c01[2 * b + 1] = (float)c1;
    }
    __syncthreads();   // red0 free again

    // second-order forward: quadratic part per color, linear part summed over colors
    double quad = 0.0, Smd2 = 0.0;
    #pragma unroll
    for (int c = 0; c < 4; ++c) {
        const double md = S[2 + c] / N;
        const double qd = 2.0 * S[6 + c] / N;
        const double vd = 2.0 * (S[6 + c] - N * m * md) / N1;
        const double ud = md * a0 + vd * a1 + qd * a2;
        quad += gpp * ud * ud;
        Smd2 += md * md;
    }
    const double Smdd = S[10] / N;
    const double Sqdd = 2.0 * (S[11] + S[12]) / N;
    const double Svdd = 2.0 * (S[11] - N * Smd2 + S[12] - m * S[10]) / N1;
    const double Sudd = Smdd * a0 + Svdd * a1 + Sqdd * a2;

    red0[t] = w2 * (quad + gp * Sudd);
    __syncthreads();
    if (t == 0) {
        double L = 0.0;
        for (int i = 0; i < 64; ++i) L += red0[i];
        out[b * 4097 + 4096] = (float)L;
    }
}

// ---------------------------------------------------------------------------
// Pass C: grad = g*da + Stencil(g*db), g = c0 + c1*h. grid (16, BATCH), 256 thr.
// ---------------------------------------------------------------------------
__global__ void passC_kernel(float* __restrict__ out)
{
    const int b = blockIdx.y;
    const int s = blockIdx.x * 256 + threadIdx.x;
    const int i = s >> 6, j = s & 63;
    const int iM = (i + 63) & 63, iP = (i + 1) & 63;
    const int jM = (j + 63) & 63, jP = (j + 1) & 63;

    const float c0 = g_c01[2 * b], c1 = g_c01[2 * b + 1];
    const float* h  = g_h  + b * NS;
    const float* db = g_db + b * NS;

    const int nU = (iM << 6) | j, nD = (iP << 6) | j;
    const int nL = (i << 6) | jM, nR = (i << 6) | jP;

    const float gs = fmaf(c1, h[s], c0);
    const float st = fmaf(c1, h[nU], c0) * db[nU]
                   + fmaf(c1, h[nD], c0) * db[nD]
                   + fmaf(c1, h[nL], c0) * db[nL]
                   + fmaf(c1, h[nR], c0) * db[nR]
                   - 4.0f * gs * db[s];
    out[b * 4097 + s] = fmaf(gs, g_da[b * NS + s], st);
}

// ---------------------------------------------------------------------------
extern "C" void kernel_launch(void* const* d_in, const int* in_sizes, int n_in,
                              void* d_out, int out_size)
{
    (void)in_sizes; (void)n_in; (void)out_size;
    const float* x     = (const float*)d_in[0];
    const int*   signs = (const int*)  d_in[1];
    const float* W1    = (const float*)d_in[2];
    const float* b1    = (const float*)d_in[3];
    const float* W2    = (const float*)d_in[4];
    const float* b2    = (const float*)d_in[5];
    const float* W3    = (const float*)d_in[6];
    const float* b3    = (const float*)d_in[7];
    const float* aW1   = (const float*)d_in[8];
    const float* ab1   = (const float*)d_in[9];
    const float* aW2   = (const float*)d_in[10];
    float* out = (float*)d_out;

    cudaFuncSetAttribute(passA_kernel, cudaFuncAttributeMaxDynamicSharedMemorySize, SMEMSZ);

    passA_kernel<<<dim3(NBLK, BATCH), 256, SMEMSZ>>>(x, signs, W1, b1, W2, b2, W3, b3);
    passB_kernel<<<BATCH, 64>>>(aW1, ab1, aW2, out);
    passC_kernel<<<dim3(16, BATCH), 256>>>(out);
}

// round 10
// speedup vs baseline: 1.9101x; 1.4371x over previous
#include <cuda_runtime.h>
#include <cuda_bf16.h>
#include <math.h>
#include <stdint.h>

#define BATCH 64
#define NS 4096
#define CPB 16           // CTAs per batch
#define NPART 13
#define BN (BATCH*NS)

// scratch (device globals; no allocations allowed)
__device__ float g_h [BN];
__device__ float g_da[BN];
__device__ float g_db[BN];
__device__ float g_part[BATCH][CPB][NPART];
__device__ float g_c01[BATCH*2];

// ---------------- smem layout (bytes) ----------------
#define OFF_BHI   0        // W2^T hi: 128 n-rows x 256B, pair-permuted k
#define OFF_BLO   32768
#define OFF_A     65536    // per warp 8KB: Ahi 16x256B, Alo +4096
#define OFF_WAS   131072
#define OFF_WBS   131584
#define OFF_B1S   132096
#define OFF_B2S   132608
#define OFF_W3S   133120
#define OFF_WPART 133632   // 8 warps x 13 floats
#define SMEMSZ    134144

__device__ __forceinline__ void gelu3f(float x, float& v, float& d1, float& d2) {
    float Phi = normcdff(x);
    float ph  = 0.3989422804014326779f * __expf(-0.5f * x * x);
    v  = x * Phi;
    d1 = fmaf(x, ph, Phi);
    d2 = (2.0f - x * x) * ph;
}
__device__ __forceinline__ uint32_t cvt2(float hi, float lo) {
    uint32_t r;
    asm("cvt.rn.bf16x2.f32 %0, %1, %2;" : "=r"(r) : "f"(hi), "f"(lo));
    return r;
}
__device__ __forceinline__ void mma16816(float* d, uint32_t a0, uint32_t a1,
                                         uint32_t a2, uint32_t a3,
                                         uint32_t b0, uint32_t b1) {
    asm volatile(
        "mma.sync.aligned.m16n8k16.row.col.f32.bf16.bf16.f32 "
        "{%0,%1,%2,%3}, {%4,%5,%6,%7}, {%8,%9}, {%0,%1,%2,%3};"
        : "+f"(d[0]), "+f"(d[1]), "+f"(d[2]), "+f"(d[3])
        : "r"(a0), "r"(a1), "r"(a2), "r"(a3), "r"(b0), "r"(b1));
}

// pair-permuted k layout: within a 16-k block, pair p=(2m,2m+1), q=m&7 goes to
// dword 2*(q&3)+(q>>2) of the 32B chunk; chunk index = (kstep ^ (row&7)).
// => LDS.64 at rowbase + ((K^(row&7))<<5) + 8*tq returns (frag_q=tq, frag_q=tq+4).

// ---------------------------------------------------------------------------
// Pass A (mma.sync): grid (CPB, BATCH), 256 threads = 8 independent warps.
// Warp-iter: 4 sites (16 rows = 4 types x 4 sites, row = 4*tt + sI).
// ---------------------------------------------------------------------------
__global__ void __launch_bounds__(256, 1)
passA_mma(const float* __restrict__ x, const int* __restrict__ signs,
          const float* __restrict__ W1, const float* __restrict__ b1,
          const float* __restrict__ W2, const float* __restrict__ b2,
          const float* __restrict__ W3, const float* __restrict__ b3)
{
    extern __shared__ __align__(256) char sm[];
    float* smf = (float*)sm;
    const int tid  = threadIdx.x;
    const int warp = tid >> 5;
    const int lane = tid & 31;
    const int g    = lane >> 2;      // fragment group (0..7)
    const int tq   = lane & 3;       // thread-in-group
    const int b    = blockIdx.y;

    // ---- stage W2^T hi/lo into pair-permuted smem ----
    for (int idx = tid; idx < 128 * 128; idx += 256) {
        const int j = idx >> 7, n = idx & 127;      // W2[j][n], k-dim = j
        const float v = W2[idx];
        const __nv_bfloat16 hb = __float2bfloat16(v);
        const __nv_bfloat16 lb = __float2bfloat16(v - __bfloat162float(hb));
        const int pairI = (j >> 1) & 7;
        const int dw    = 2 * (pairI & 3) + (pairI >> 2);
        const uint32_t off = (uint32_t)(n * 256 + (((j >> 4) ^ (n & 7)) << 5)
                                        + dw * 4 + (j & 1) * 2);
        *(__nv_bfloat16*)(sm + OFF_BHI + off) = hb;
        *(__nv_bfloat16*)(sm + OFF_BLO + off) = lb;
    }
    if (tid < 128) {
        smf[(OFF_WAS >> 2) + tid] = W1[tid] + W1[256 + tid] + W1[384 + tid];
        smf[(OFF_WBS >> 2) + tid] = W1[128 + tid];
        smf[(OFF_B1S >> 2) + tid] = b1[tid];
        smf[(OFF_B2S >> 2) + tid] = b2[tid];
        smf[(OFF_W3S >> 2) + tid] = W3[tid];
    }
    __syncthreads();

    const float b3v = b3[0];
    const float* xb = x + b * NS;
    const int* sgb  = signs + b * NS;

    char* Ahi = sm + OFF_A + warp * 8192;
    char* Alo = Ahi + 4096;

    // this lane's 4 hidden-1 columns: j0=16K+2q, +1, +8, +9
    const int Kl = g, ql = tq;   // lane's K-block = lane>>2, pair slot = lane&3
    const int j0 = 16 * Kl + 2 * ql;
    float wa4[4], wb4[4], b14[4], wd4[4];
    {
        const int jj[4] = {j0, j0 + 1, j0 + 8, j0 + 9};
        #pragma unroll
        for (int c = 0; c < 4; ++c) {
            wa4[c] = smf[(OFF_WAS >> 2) + jj[c]];
            wb4[c] = smf[(OFF_WBS >> 2) + jj[c]];
            b14[c] = smf[(OFF_B1S >> 2) + jj[c]];
            wd4[c] = wa4[c] - 4.0f * wb4[c];
        }
    }

    // per-thread stat partials (leaders only nonzero)
    float aSh = 0.f, aSh2 = 0.f, aH2s = 0.f, aHd2s = 0.f, aHH2s = 0.f;
    float aHd[4] = {0,0,0,0}, aHHd[4] = {0,0,0,0};

    for (int it = 0; it < 8; ++it) {
        const int sb = (((blockIdx.x * 8 + warp) * 8) + it) * 4;

        // ---- per-lane site aux (site sI = lane&3, replicated x8) ----
        float xcL, lapL, alphaL, bet1L, bet2L, scL; int dL;
        {
            const int sI = lane & 3;
            const int s  = sb + sI;
            const int i  = s >> 6, j = s & 63;
            const int iM = (i + 63) & 63, iP = (i + 1) & 63;
            const int jM = (j + 63) & 63, jP = (j + 1) & 63;
            xcL  = xb[s];
            lapL = xb[(iM << 6) | j] + xb[(iP << 6) | j]
                 + xb[(i << 6) | jM] + xb[(i << 6) | jP] - 4.0f * xcL;
            dL     = ((i & 1) << 1) | (j & 1);
            alphaL = (float)(2 * sgb[dL * BN + s] - 1);
            bet1L  = (float)(2 * sgb[(dL ^ 1) * BN + ((i << 6) | jM)]
                           + 2 * sgb[(dL ^ 1) * BN + ((i << 6) | jP)] - 2);
            bet2L  = (float)(2 * sgb[(dL ^ 2) * BN + ((iM << 6) | j)]
                           + 2 * sgb[(dL ^ 2) * BN + ((iP << 6) | j)] - 2);
            scL = bet1L * bet1L + bet2L * bet2L;
        }

        __syncwarp();   // previous iter's k-loop reads of A must be done

        // ---- layer 1: build A tile (16 rows x 128 k, bf16 hi/lo) ----
        #pragma unroll
        for (int sI = 0; sI < 4; ++sI) {
            const float xc  = __shfl_sync(0xffffffffu, xcL,  sI);
            const float lap = __shfl_sync(0xffffffffu, lapL, sI);
            const float sc  = __shfl_sync(0xffffffffu, scL,  sI);
            float vv[4][4];
            #pragma unroll
            for (int c = 0; c < 4; ++c) {
                const float p1 = fmaf(xc, wa4[c], fmaf(lap, wb4[c], b14[c]));
                float a1, gp, gpp;
                gelu3f(p1, a1, gp, gpp);
                vv[0][c] = a1;
                vv[1][c] = gp * wd4[c];
                vv[2][c] = gp * wb4[c];
                vv[3][c] = gpp * fmaf(sc, wb4[c] * wb4[c], wd4[c] * wd4[c]);
            }
            #pragma unroll
            for (int tt = 0; tt < 4; ++tt) {
                const int row = 4 * tt + sI;
                const uint32_t off = (uint32_t)(row * 256
                                    + ((Kl ^ (row & 7)) << 5) + 8 * ql);
                const uint32_t h0 = cvt2(vv[tt][1], vv[tt][0]);
                const uint32_t h1 = cvt2(vv[tt][3], vv[tt][2]);
                const float f0 = __uint_as_float(h0 << 16);
                const float f1 = __uint_as_float(h0 & 0xffff0000u);
                const float f2 = __uint_as_float(h1 << 16);
                const float f3 = __uint_as_float(h1 & 0xffff0000u);
                const uint32_t l0 = cvt2(vv[tt][1] - f1, vv[tt][0] - f0);
                const uint32_t l1 = cvt2(vv[tt][3] - f3, vv[tt][2] - f2);
                *(uint2*)(Ahi + off) = make_uint2(h0, h1);
                *(uint2*)(Alo + off) = make_uint2(l0, l1);
            }
        }
        __syncwarp();

        // ---- MMA: D[16,128] = A @ W2 (3-term split) ----
        float acc[16][4];
        #pragma unroll
        for (int n = 0; n < 16; ++n)
            #pragma unroll
            for (int c = 0; c < 4; ++c) acc[n][c] = 0.0f;

        for (int K = 0; K < 8; ++K) {
            const uint2 Ah0 = *(uint2*)(Ahi + g * 256 + ((K ^ (g & 7)) << 5) + 8 * tq);
            const uint2 Ah1 = *(uint2*)(Ahi + (g + 8) * 256 + ((K ^ ((g + 8) & 7)) << 5) + 8 * tq);
            const uint2 Al0 = *(uint2*)(Alo + g * 256 + ((K ^ (g & 7)) << 5) + 8 * tq);
            const uint2 Al1 = *(uint2*)(Alo + (g + 8) * 256 + ((K ^ ((g + 8) & 7)) << 5) + 8 * tq);
            const uint32_t bcom = (uint32_t)(256 * g + ((K ^ (g & 7)) << 5) + 8 * tq);
            #pragma unroll
            for (int n = 0; n < 16; ++n) {
                const uint32_t boff = bcom + 2048u * n;
                const uint2 Bh = *(uint2*)(sm + OFF_BHI + boff);
                mma16816(acc[n], Ah0.x, Ah1.x, Ah0.y, Ah1.y, Bh.x, Bh.y);
                mma16816(acc[n], Al0.x, Al1.x, Al0.y, Al1.y, Bh.x, Bh.y);
                const uint2 Bl = *(uint2*)(sm + OFF_BLO + boff);
                mma16816(acc[n], Ah0.x, Ah1.x, Ah0.y, Ah1.y, Bl.x, Bl.y);
            }
        }

        // ---- epilogue ----
        // lanes 0-15:  c0c1 = A-row (site g),  c2c3 = Q-row (site g)
        // lanes 16-31: c0c1 = P-row (site g-4), c2c3 = U-row (site g-4)
        float hA = 0.f, S1a = 0.f, S2a = 0.f, S1b = 0.f, S2b = 0.f;
        #pragma unroll
        for (int n = 0; n < 16; ++n) {
            const int k0 = 8 * n + 2 * tq;
            const float2 b2p = *(const float2*)(smf + (OFF_B2S >> 2) + k0);
            const float2 w3p = *(const float2*)(smf + (OFF_W3S >> 2) + k0);
            float a20, gp0, gpp0, a21, gp1, gpp1;
            gelu3f(acc[n][0] + b2p.x, a20, gp0, gpp0);
            gelu3f(acc[n][1] + b2p.y, a21, gp1, gpp1);
            hA += a20 * w3p.x + a21 * w3p.y;
            float gw0 = gp0 * w3p.x, gg0 = gpp0 * w3p.x;
            float gw1 = gp1 * w3p.y, gg1 = gpp1 * w3p.y;
            gw0 = __shfl_sync(0xffffffffu, gw0, lane & 15);
            gg0 = __shfl_sync(0xffffffffu, gg0, lane & 15);
            gw1 = __shfl_sync(0xffffffffu, gw1, lane & 15);
            gg1 = __shfl_sync(0xffffffffu, gg1, lane & 15);
            S1a = fmaf(acc[n][0], gw0, fmaf(acc[n][1], gw1, S1a));
            S2a = fmaf(acc[n][0] * acc[n][0], gg0, fmaf(acc[n][1] * acc[n][1], gg1, S2a));
            S1b = fmaf(acc[n][2], gw0, fmaf(acc[n][3], gw1, S1b));
            S2b = fmaf(acc[n][2] * acc[n][2], gg0, fmaf(acc[n][3] * acc[n][3], gg1, S2b));
        }
        // reduce over tq (4 lanes per row)
        #pragma unroll
        for (int o = 1; o <= 2; o <<= 1) {
            hA  += __shfl_xor_sync(0xffffffffu, hA,  o);
            S1a += __shfl_xor_sync(0xffffffffu, S1a, o);
            S2a += __shfl_xor_sync(0xffffffffu, S2a, o);
            S1b += __shfl_xor_sync(0xffffffffu, S1b, o);
            S2b += __shfl_xor_sync(0xffffffffu, S2b, o);
        }
        // cross-half gathers (valid for lanes 0-15)
        const float Pd = __shfl_sync(0xffffffffu, S1a, lane | 16);
        const float PP = __shfl_sync(0xffffffffu, S2a, lane | 16);
        const float UU = __shfl_sync(0xffffffffu, S1b, lane | 16);
        // site aux to leaders (leader lane 4s needs site s = lane>>2)
        const float al  = __shfl_sync(0xffffffffu, alphaL, lane >> 2);
        const float bb1 = __shfl_sync(0xffffffffu, bet1L,  lane >> 2);
        const float bb2 = __shfl_sync(0xffffffffu, bet2L,  lane >> 2);
        const float scv = __shfl_sync(0xffffffffu, scL,    lane >> 2);
        const int   dv  = __shfl_sync(0xffffffffu, dL,     lane >> 2);

        if ((lane & 0x13) == 0) {    // lanes 0,4,8,12 : site = lane>>2
            const int s = sb + (lane >> 2);
            const float h  = hA + b3v;
            const float Qd = S1b, QQ = S2b;
            g_h [b * NS + s] = h;
            g_da[b * NS + s] = Pd + 4.0f * Qd;
            g_db[b * NS + s] = Qd;
            aSh  += h;
            aSh2 += h * h;
            #pragma unroll
            for (int cc = 0; cc < 4; ++cc) {
                float hd;
                if      (cc == dv)       hd = al  * Pd;
                else if (cc == (dv ^ 1)) hd = bb1 * Qd;
                else if (cc == (dv ^ 2)) hd = bb2 * Qd;
                else                     hd = 0.0f;
                aHd [cc] += hd;
                aHHd[cc] += h * hd;
            }
            const float h2t = PP + scv * QQ + UU;
            aH2s  += h2t;
            aHd2s += fmaf(scv, Qd * Qd, Pd * Pd);
            aHH2s += h * h2t;
        }
    }

    // warp-level reduction of the 13 partials (non-leader lanes hold zeros)
    float pr[NPART];
    pr[0] = aSh; pr[1] = aSh2;
    #pragma unroll
    for (int c = 0; c < 4; ++c) { pr[2 + c] = aHd[c]; pr[6 + c] = aHHd[c]; }
    pr[10] = aH2s; pr[11] = aHd2s; pr[12] = aHH2s;
    #pragma unroll
    for (int k = 0; k < NPART; ++k) {
        #pragma unroll
        for (int off = 16; off >= 1; off >>= 1)
            pr[k] += __shfl_xor_sync(0xffffffffu, pr[k], off);
    }
    if (lane == 0) {
        #pragma unroll
        for (int k = 0; k < NPART; ++k)
            smf[(OFF_WPART >> 2) + warp * NPART + k] = pr[k];
    }
    __syncthreads();
    if (tid < NPART) {
        float sum = 0.0f;
        #pragma unroll
        for (int w = 0; w < 8; ++w) sum += smf[(OFF_WPART >> 2) + w * NPART + tid];
        g_part[b][blockIdx.x][tid] = sum;
    }
}

// ---------------------------------------------------------------------------
// Pass B: per-batch stats + agg backward (c0,c1) + second-order forward.
// ---------------------------------------------------------------------------
__global__ void passB_kernel(const float* __restrict__ aW1, const float* __restrict__ ab1,
                             const float* __restrict__ aW2, float* __restrict__ out)
{
    __shared__ double S[NPART];
    __shared__ double red0[64], red1[64], red2[64];

    const int b = blockIdx.x, t = threadIdx.x;
    if (t < NPART) {
        double s = 0.0;
        for (int k = 0; k < CPB; ++k) s += (double)g_part[b][k][t];
        S[t] = s;
    }
    __syncthreads();

    const double N = 4096.0, N1 = 4095.0;
    const double m = S[0] / N;
    const double q = S[1] / N;
    const double v = (S[1] - N * m * m) / N1;

    const double a0 = (double)aW1[t], a1 = (double)aW1[64 + t], a2 = (double)aW1[128 + t];
    const double u  = m * a0 + v * a1 + q * a2 + (double)ab1[t];
    const double Phi = normcdf(u);
    const double ph  = 0.39894228040143267794 * exp(-0.5 * u * u);
    const double gp  = Phi + u * ph;
    const double gpp = (2.0 - u * u) * ph;
    const double w2  = (double)aW2[t];

    red0[t] = a0 * gp * w2;
    red1[t] = a1 * gp * w2;
    red2[t] = a2 * gp * w2;
    __syncthreads();
    if (t == 0) {
        double dm = 0, dv = 0, dq = 0;
        for (int i = 0; i < 64; ++i) { dm += red0[i]; dv += red1[i]; dq += red2[i]; }
        g_c01[2 * b]     = (float)(dm / N - 2.0 * dv * m / N1);
        g_c01[2 * b + 1] = (float)(2.0 * dv / N1 + 2.0 * dq / N);
    }
    __syncthreads();

    double quad = 0.0, Smd2 = 0.0;
    #pragma unroll
    for (int c = 0; c < 4; ++c) {
        const double md = S[2 + c] / N;
        const double qd = 2.0 * S[6 + c] / N;
        const double vd = 2.0 * (S[6 + c] - N * m * md) / N1;
        const double ud = md * a0 + vd * a1 + qd * a2;
        quad += gpp * ud * ud;
        Smd2 += md * md;
    }
    const double Smdd = S[10] / N;
    const double Sqdd = 2.0 * (S[11] + S[12]) / N;
    const double Svdd = 2.0 * (S[11] - N * Smd2 + S[12] - m * S[10]) / N1;
    const double Sudd = Smdd * a0 + Svdd * a1 + Sqdd * a2;

    red0[t] = w2 * (quad + gp * Sudd);
    __syncthreads();
    if (t == 0) {
        double L = 0.0;
        for (int i = 0; i < 64; ++i) L += red0[i];
        out[b * 4097 + 4096] = (float)L;
    }
}

// ---------------------------------------------------------------------------
// Pass C: grad = g*da + Stencil(g*db), g = c0 + c1*h.
// ---------------------------------------------------------------------------
__global__ void passC_kernel(float* __restrict__ out)
{
    const int b = blockIdx.y;
    const int s = blockIdx.x * 256 + threadIdx.x;
    const int i = s >> 6, j = s & 63;
    const int iM = (i + 63) & 63, iP = (i + 1) & 63;
    const int jM = (j + 63) & 63, jP = (j + 1) & 63;

    const float c0 = g_c01[2 * b], c1 = g_c01[2 * b + 1];
    const float* h  = g_h  + b * NS;
    const float* db = g_db + b * NS;

    const int nU = (iM << 6) | j, nD = (iP << 6) | j;
    const int nL = (i << 6) | jM, nR = (i << 6) | jP;

    const float gs = fmaf(c1, h[s], c0);
    const float st = fmaf(c1, h[nU], c0) * db[nU]
                   + fmaf(c1, h[nD], c0) * db[nD]
                   + fmaf(c1, h[nL], c0) * db[nL]
                   + fmaf(c1, h[nR], c0) * db[nR]
                   - 4.0f * gs * db[s];
    out[b * 4097 + s] = fmaf(gs, g_da[b * NS + s], st);
}

// ---------------------------------------------------------------------------
extern "C" void kernel_launch(void* const* d_in, const int* in_sizes, int n_in,
                              void* d_out, int out_size)
{
    (void)in_sizes; (void)n_in; (void)out_size;
    const float* x     = (const float*)d_in[0];
    const int*   signs = (const int*)  d_in[1];
    const float* W1    = (const float*)d_in[2];
    const float* b1    = (const float*)d_in[3];
    const float* W2    = (const float*)d_in[4];
    const float* b2    = (const float*)d_in[5];
    const float* W3    = (const float*)d_in[6];
    const float* b3    = (const float*)d_in[7];
    const float* aW1   = (const float*)d_in[8];
    const float* ab1   = (const float*)d_in[9];
    const float* aW2   = (const float*)d_in[10];
    float* out = (float*)d_out;

    cudaFuncSetAttribute(passA_mma, cudaFuncAttributeMaxDynamicSharedMemorySize, SMEMSZ);

    passA_mma<<<dim3(CPB, BATCH), 256, SMEMSZ>>>(x, signs, W1, b1, W2, b2, W3, b3);
    passB_kernel<<<BATCH, 64>>>(aW1, ab1, aW2, out);
    passC_kernel<<<dim3(16, BATCH), 256>>>(out);
}